// round 14
// baseline (speedup 1.0000x reference)
#include <cuda_runtime.h>
#include <cuda_bf16.h>

// SSIM preservation loss: 1 - mean(ssim_map(clean, adversarial))
// 4-channel transform: convolve s=x+y, d=x-y, s^2, d^2. Separable 11x11
// Gaussian. Vertical: packed-f32x2 register rings (squares on the fly).
// Horizontal: scalar FFMA-imm from LDS.64 halves. 2 rows per barrier.
// R14: x4-scaled SSIM (no HALF const), cur/nxt row pipeline, own-register
// f3 on second row, ROWS_PER_BLOCK=8 (wave tail 5.6%->1.2%).

#define IMG_W 512
#define IMG_H 512
#define ROWS_PER_BLOCK 8
#define STRIPS (IMG_H / ROWS_PER_BLOCK)   // 64
#define NPLANES 96                        // 32 batch * 3 channels
#define NBLOCKS (NPLANES * STRIPS)        // 6144
#define NTHREADS 256
#define TOTAL_PIX 25165824.0              // 32*3*512*512

// 1D Gaussian weights, sigma=1.5, normalized.
#define KW0 0.00102838f
#define KW1 0.00759876f
#define KW2 0.03600077f
#define KW3 0.10936070f
#define KW4 0.21300560f
#define KW5 0.26601170f

typedef unsigned long long u64;

__device__ double g_partials[NBLOCKS];
__device__ unsigned int g_ticket = 0;

// ---------- packed f32x2 primitives ----------
__device__ __forceinline__ u64 pack2(float lo, float hi) {
    u64 r; asm("mov.b64 %0, {%1, %2};" : "=l"(r) : "f"(lo), "f"(hi)); return r;
}
__device__ __forceinline__ void unpack2(u64 v, float& lo, float& hi) {
    asm("mov.b64 {%0, %1}, %2;" : "=f"(lo), "=f"(hi) : "l"(v));
}
__device__ __forceinline__ u64 fma2(u64 a, u64 b, u64 c) {
    u64 d; asm("fma.rn.f32x2 %0, %1, %2, %3;" : "=l"(d) : "l"(a), "l"(b), "l"(c)); return d;
}
__device__ __forceinline__ u64 mul2(u64 a, u64 b) {
    u64 d; asm("mul.rn.f32x2 %0, %1, %2;" : "=l"(d) : "l"(a), "l"(b)); return d;
}
__device__ __forceinline__ u64 add2(u64 a, u64 b) {
    u64 d; asm("add.rn.f32x2 %0, %1, %2;" : "=l"(d) : "l"(a), "l"(b)); return d;
}
__device__ __forceinline__ float frcp(float x) {
    float r; asm("rcp.approx.f32 %0, %1;" : "=f"(r) : "f"(x)); return r;
}

__global__ void __launch_bounds__(NTHREADS, 2)
ssim_main(const float* __restrict__ X, const float* __restrict__ Y,
          float* __restrict__ out) {
    const int b     = blockIdx.x;
    const int plane = b >> 6;        // / STRIPS
    const int strip = b & 63;        // % STRIPS
    const int r0    = strip * ROWS_PER_BLOCK;
    const int t     = threadIdx.x;
    const int c0    = t * 2;

    const float* __restrict__ px = X + (size_t)plane * (IMG_H * IMG_W);
    const float* __restrict__ py = Y + (size_t)plane * (IMG_H * IMG_W);

    // Packed weights (vertical FFMA2 needs register weights).
    const u64 WV0 = pack2(KW0, KW0);
    const u64 WV1 = pack2(KW1, KW1);
    const u64 WV2 = pack2(KW2, KW2);
    const u64 WV3 = pack2(KW3, KW3);
    const u64 WV4 = pack2(KW4, KW4);
    const u64 WV5 = pack2(KW5, KW5);
    const u64 NEG1v = pack2(-1.0f, -1.0f);
    const u64 C1x2  = pack2(2.0e-4f, 2.0e-4f);   // 2*C1
    const u64 C2x2  = pack2(1.8e-3f, 1.8e-3f);   // 2*C2

    // 4 row buffers (2 row-pairs, alternating): index = 8 + col.
    __shared__ float vbuf[4][4][528];
    __shared__ float warpsum[8];
    __shared__ bool  is_last;
    __shared__ double sd[NTHREADS];

    if (t < 4) {
        #pragma unroll
        for (int bb = 0; bb < 4; bb++) {
            #pragma unroll
            for (int i = 0; i < 8; i++) {
                vbuf[bb][t][i] = 0.0f;
                vbuf[bb][t][520 + i] = 0.0f;
            }
        }
    }

    // Register rings: 11 rows x (2 cols packed), channels s = x+y, d = x-y.
    u64 rs[11], rd[11];

    // Prime slots 0..9 with input rows r0-5 .. r0+4 (zero outside image).
    #pragma unroll
    for (int k = 0; k < 10; k++) {
        int ir = r0 - 5 + k;
        u64 vx = 0ull, vy = 0ull;
        if ((unsigned)ir < (unsigned)IMG_H) {
            vx = *(const u64*)(px + ir * IMG_W + c0);
            vy = *(const u64*)(py + ir * IMG_W + c0);
        }
        rs[k] = add2(vx, vy);
        rd[k] = fma2(vy, NEG1v, vx);
    }

    // Two-row pipeline: cur = row r0+5, nxt = row r0+6.
    u64 curx = 0ull, cury = 0ull, nxtx = 0ull, nxty = 0ull;
    {
        int ira = r0 + 5, irb = r0 + 6;
        if (ira < IMG_H) {
            curx = *(const u64*)(px + ira * IMG_W + c0);
            cury = *(const u64*)(py + ira * IMG_W + c0);
        }
        if (irb < IMG_H) {
            nxtx = *(const u64*)(px + irb * IMG_W + c0);
            nxty = *(const u64*)(py + irb * IMG_W + c0);
        }
    }

    u64 accv = 0ull;   // packed (0.0f, 0.0f)

    #pragma unroll
    for (int rp = 0; rp < ROWS_PER_BLOCK / 2; rp++) {
        const int r  = 2 * rp;
        const int pb = rp & 1;           // buffer pair select: {0,1} or {2,3}

        // Own-register copies of second row's vertical outputs (f3 source).
        u64 oms = 0ull, omd = 0ull, oes = 0ull, oed = 0ull;

        // ---- vertical pass for the two rows of this pair ----
        #pragma unroll
        for (int sub = 0; sub < 2; sub++) {
            const int rr = r + sub;
            // push current row (r0+rr+5) into ring slot (rr+10)%11
            {
                const int sl = (rr + 10) % 11;
                u64 ax = sub ? nxtx : curx;
                u64 ay = sub ? nxty : cury;
                rs[sl] = add2(ax, ay);
                rd[sl] = fma2(ay, NEG1v, ax);
            }
            // refill the consumed pipeline slot with row (r0+rr+7)
            {
                int irn = r0 + rr + 7;
                u64 lx = 0ull, ly = 0ull;
                if ((unsigned)irn < (unsigned)IMG_H) {
                    lx = *(const u64*)(px + irn * IMG_W + c0);
                    ly = *(const u64*)(py + irn * IMG_W + c0);
                }
                if (sub == 0) { curx = lx; cury = ly; }   // becomes row rr+7? no:
                else          { nxtx = lx; nxty = ly; }
            }
            // 11-tap vertical conv (packed, squares on the fly)
            u64 ms, md, es, ed;
            {
                const int s0 = rr % 11;
                u64 sv = rs[s0], dv = rd[s0];
                ms = mul2(WV0, sv);
                md = mul2(WV0, dv);
                es = mul2(WV0, mul2(sv, sv));
                ed = mul2(WV0, mul2(dv, dv));
            }
            #pragma unroll
            for (int tt = 1; tt < 11; tt++) {
                const int sl = (rr + tt) % 11;
                const u64 w = (tt == 1 || tt == 9) ? WV1 :
                              (tt == 2 || tt == 8) ? WV2 :
                              (tt == 3 || tt == 7) ? WV3 :
                              (tt == 4 || tt == 6) ? WV4 :
                              (tt == 5)            ? WV5 : WV0;
                u64 sv = rs[sl], dv = rd[sl];
                ms = fma2(w, sv, ms);
                md = fma2(w, dv, md);
                es = fma2(w, mul2(sv, sv), es);
                ed = fma2(w, mul2(dv, dv), ed);
            }
            const int buf = 2 * pb + sub;
            *(u64*)(&vbuf[buf][0][8 + c0]) = ms;
            *(u64*)(&vbuf[buf][1][8 + c0]) = md;
            *(u64*)(&vbuf[buf][2][8 + c0]) = es;
            *(u64*)(&vbuf[buf][3][8 + c0]) = ed;
            if (sub == 1) { oms = ms; omd = md; oes = es; oed = ed; }
        }

        __syncthreads();   // one barrier per 2 rows

        // ---- horizontal pass + SSIM for both rows (scalar FFMA-imm) ----
        #pragma unroll
        for (int sub = 0; sub < 2; sub++) {
            const int buf = 2 * pb + sub;
            const u64 ownv[4] = {oms, omd, oes, oed};
            u64 hr2[4];
            #pragma unroll
            for (int q = 0; q < 4; q++) {
                const float2* vb = (const float2*)(&vbuf[buf][q][8 + c0 - 6]);
                float2 f0 = vb[0];   // v[-6], v[-5]
                float2 f1 = vb[1];   // v[-4], v[-3]
                float2 f2 = vb[2];   // v[-2], v[-1]
                float2 f3;           // v[0],  v[1]  (own pair)
                if (sub == 1) { unpack2(ownv[q], f3.x, f3.y); }
                else          { f3 = vb[3]; }
                float2 f4 = vb[4];   // v[2],  v[3]
                float2 f5 = vb[5];   // v[4],  v[5]
                float2 f6 = vb[6];   // v[6],  v[7]

                float p0 = KW0 * f0.y;
                p0 = fmaf(KW1, f1.x, p0);
                p0 = fmaf(KW2, f1.y, p0);
                p0 = fmaf(KW3, f2.x, p0);
                p0 = fmaf(KW4, f2.y, p0);
                p0 = fmaf(KW5, f3.x, p0);
                p0 = fmaf(KW4, f3.y, p0);
                p0 = fmaf(KW3, f4.x, p0);
                p0 = fmaf(KW2, f4.y, p0);
                p0 = fmaf(KW1, f5.x, p0);
                p0 = fmaf(KW0, f5.y, p0);

                float p1 = KW0 * f1.x;
                p1 = fmaf(KW1, f1.y, p1);
                p1 = fmaf(KW2, f2.x, p1);
                p1 = fmaf(KW3, f2.y, p1);
                p1 = fmaf(KW4, f3.x, p1);
                p1 = fmaf(KW5, f3.y, p1);
                p1 = fmaf(KW4, f4.x, p1);
                p1 = fmaf(KW3, f4.y, p1);
                p1 = fmaf(KW2, f5.x, p1);
                p1 = fmaf(KW1, f5.y, p1);
                p1 = fmaf(KW0, f6.x, p1);

                hr2[q] = pack2(p0, p1);
            }

            // ---- SSIM, x4-scaled (bit-identical quotient) ----
            {
                u64 MS = hr2[0], MD = hr2[1], ES = hr2[2], ED = hr2[3];
                u64 A  = mul2(MS, MS);
                u64 B  = mul2(MD, MD);
                u64 P2 = add2(A, B);                    // 2(mu1^2+mu2^2)
                u64 Q2 = fma2(B, NEG1v, A);             // 4*mu1*mu2
                u64 SE = add2(ES, ED);
                u64 DE = fma2(ED, NEG1v, ES);
                u64 R2 = fma2(P2, NEG1v, SE);           // 2(sig1+sig2)
                u64 T2 = fma2(Q2, NEG1v, DE);           // 4*sig12
                u64 num = mul2(add2(Q2, C1x2), add2(T2, C2x2));
                u64 den = mul2(add2(P2, C1x2), add2(R2, C2x2));
                float dlo, dhi;
                unpack2(den, dlo, dhi);
                u64 rcpv = pack2(frcp(dlo), frcp(dhi));
                accv = fma2(num, rcpv, accv);
            }
        }
    }

    float alo, ahi;
    unpack2(accv, alo, ahi);
    float acc = alo + ahi;

    // ---- deterministic block reduction ----
    #pragma unroll
    for (int off = 16; off > 0; off >>= 1)
        acc += __shfl_xor_sync(0xffffffffu, acc, off);
    if ((t & 31) == 0) warpsum[t >> 5] = acc;
    __syncthreads();
    if (t == 0) {
        float s = 0.0f;
        #pragma unroll
        for (int i = 0; i < 8; i++) s += warpsum[i];
        g_partials[b] = (double)s;
    }

    // ---- fused finalize: last block sums all partials (deterministic) ----
    __threadfence();
    if (t == 0) {
        unsigned int old = atomicAdd(&g_ticket, 1u);
        is_last = (old == NBLOCKS - 1);
    }
    __syncthreads();
    if (is_last) {
        double sm = 0.0;
        for (int i = t; i < NBLOCKS; i += NTHREADS) sm += g_partials[i];
        sd[t] = sm;
        __syncthreads();
        #pragma unroll
        for (int off = NTHREADS / 2; off > 0; off >>= 1) {
            if (t < off) sd[t] += sd[t + off];
            __syncthreads();
        }
        if (t == 0) {
            out[0] = (float)(1.0 - sd[0] / TOTAL_PIX);
            g_ticket = 0;   // reset for next graph replay
        }
    }
}

extern "C" void kernel_launch(void* const* d_in, const int* in_sizes, int n_in,
                              void* d_out, int out_size) {
    const float* clean = (const float*)d_in[0];
    const float* adv   = (const float*)d_in[1];
    ssim_main<<<NBLOCKS, NTHREADS>>>(clean, adv, (float*)d_out);
}

// round 15
// speedup vs baseline: 1.5257x; 1.5257x over previous
#include <cuda_runtime.h>
#include <cuda_bf16.h>

// SSIM preservation loss: 1 - mean(ssim_map(clean, adversarial))
// 4-channel transform: convolve s=x+y, d=x-y, s^2, d^2. Separable 11x11
// Gaussian. Vertical: packed-f32x2 register rings (squares on the fly).
// Horizontal: scalar FFMA-imm from LDS.64 halves. 2 rows per barrier.
// R15: revert ROWS_PER_BLOCK to 16 (8 killed priming amortization); keep
// x4-scaled SSIM, cur/nxt pipeline, own-register f3 on second row.

#define IMG_W 512
#define IMG_H 512
#define ROWS_PER_BLOCK 16
#define STRIPS (IMG_H / ROWS_PER_BLOCK)   // 32
#define NPLANES 96                        // 32 batch * 3 channels
#define NBLOCKS (NPLANES * STRIPS)        // 3072
#define NTHREADS 256
#define TOTAL_PIX 25165824.0              // 32*3*512*512

// 1D Gaussian weights, sigma=1.5, normalized.
#define KW0 0.00102838f
#define KW1 0.00759876f
#define KW2 0.03600077f
#define KW3 0.10936070f
#define KW4 0.21300560f
#define KW5 0.26601170f

typedef unsigned long long u64;

__device__ double g_partials[NBLOCKS];
__device__ unsigned int g_ticket = 0;

// ---------- packed f32x2 primitives ----------
__device__ __forceinline__ u64 pack2(float lo, float hi) {
    u64 r; asm("mov.b64 %0, {%1, %2};" : "=l"(r) : "f"(lo), "f"(hi)); return r;
}
__device__ __forceinline__ void unpack2(u64 v, float& lo, float& hi) {
    asm("mov.b64 {%0, %1}, %2;" : "=f"(lo), "=f"(hi) : "l"(v));
}
__device__ __forceinline__ u64 fma2(u64 a, u64 b, u64 c) {
    u64 d; asm("fma.rn.f32x2 %0, %1, %2, %3;" : "=l"(d) : "l"(a), "l"(b), "l"(c)); return d;
}
__device__ __forceinline__ u64 mul2(u64 a, u64 b) {
    u64 d; asm("mul.rn.f32x2 %0, %1, %2;" : "=l"(d) : "l"(a), "l"(b)); return d;
}
__device__ __forceinline__ u64 add2(u64 a, u64 b) {
    u64 d; asm("add.rn.f32x2 %0, %1, %2;" : "=l"(d) : "l"(a), "l"(b)); return d;
}
__device__ __forceinline__ float frcp(float x) {
    float r; asm("rcp.approx.f32 %0, %1;" : "=f"(r) : "f"(x)); return r;
}

__global__ void __launch_bounds__(NTHREADS, 2)
ssim_main(const float* __restrict__ X, const float* __restrict__ Y,
          float* __restrict__ out) {
    const int b     = blockIdx.x;
    const int plane = b >> 5;        // / STRIPS
    const int strip = b & 31;        // % STRIPS
    const int r0    = strip * ROWS_PER_BLOCK;
    const int t     = threadIdx.x;
    const int c0    = t * 2;

    const float* __restrict__ px = X + (size_t)plane * (IMG_H * IMG_W);
    const float* __restrict__ py = Y + (size_t)plane * (IMG_H * IMG_W);

    // Packed weights (vertical FFMA2 needs register weights).
    const u64 WV0 = pack2(KW0, KW0);
    const u64 WV1 = pack2(KW1, KW1);
    const u64 WV2 = pack2(KW2, KW2);
    const u64 WV3 = pack2(KW3, KW3);
    const u64 WV4 = pack2(KW4, KW4);
    const u64 WV5 = pack2(KW5, KW5);
    const u64 NEG1v = pack2(-1.0f, -1.0f);
    const u64 C1x2  = pack2(2.0e-4f, 2.0e-4f);   // 2*C1
    const u64 C2x2  = pack2(1.8e-3f, 1.8e-3f);   // 2*C2

    // 4 row buffers (2 row-pairs, alternating): index = 8 + col.
    __shared__ float vbuf[4][4][528];
    __shared__ float warpsum[8];
    __shared__ bool  is_last;
    __shared__ double sd[NTHREADS];

    if (t < 4) {
        #pragma unroll
        for (int bb = 0; bb < 4; bb++) {
            #pragma unroll
            for (int i = 0; i < 8; i++) {
                vbuf[bb][t][i] = 0.0f;
                vbuf[bb][t][520 + i] = 0.0f;
            }
        }
    }

    // Register rings: 11 rows x (2 cols packed), channels s = x+y, d = x-y.
    u64 rs[11], rd[11];

    // Prime slots 0..9 with input rows r0-5 .. r0+4 (zero outside image).
    #pragma unroll
    for (int k = 0; k < 10; k++) {
        int ir = r0 - 5 + k;
        u64 vx = 0ull, vy = 0ull;
        if ((unsigned)ir < (unsigned)IMG_H) {
            vx = *(const u64*)(px + ir * IMG_W + c0);
            vy = *(const u64*)(py + ir * IMG_W + c0);
        }
        rs[k] = add2(vx, vy);
        rd[k] = fma2(vy, NEG1v, vx);
    }

    // Two-row pipeline: cur = row r0+5, nxt = row r0+6.
    u64 curx = 0ull, cury = 0ull, nxtx = 0ull, nxty = 0ull;
    {
        int ira = r0 + 5, irb = r0 + 6;
        if (ira < IMG_H) {
            curx = *(const u64*)(px + ira * IMG_W + c0);
            cury = *(const u64*)(py + ira * IMG_W + c0);
        }
        if (irb < IMG_H) {
            nxtx = *(const u64*)(px + irb * IMG_W + c0);
            nxty = *(const u64*)(py + irb * IMG_W + c0);
        }
    }

    u64 accv = 0ull;   // packed (0.0f, 0.0f)

    #pragma unroll
    for (int rp = 0; rp < ROWS_PER_BLOCK / 2; rp++) {
        const int r  = 2 * rp;
        const int pb = rp & 1;           // buffer pair select: {0,1} or {2,3}

        // Own-register copies of second row's vertical outputs (f3 source).
        u64 oms = 0ull, omd = 0ull, oes = 0ull, oed = 0ull;

        // ---- vertical pass for the two rows of this pair ----
        #pragma unroll
        for (int sub = 0; sub < 2; sub++) {
            const int rr = r + sub;
            // push current row (r0+rr+5) into ring slot (rr+10)%11
            {
                const int sl = (rr + 10) % 11;
                u64 ax = sub ? nxtx : curx;
                u64 ay = sub ? nxty : cury;
                rs[sl] = add2(ax, ay);
                rd[sl] = fma2(ay, NEG1v, ax);
            }
            // refill the consumed pipeline slot with row (r0+rr+7)
            {
                int irn = r0 + rr + 7;
                u64 lx = 0ull, ly = 0ull;
                if ((unsigned)irn < (unsigned)IMG_H) {
                    lx = *(const u64*)(px + irn * IMG_W + c0);
                    ly = *(const u64*)(py + irn * IMG_W + c0);
                }
                if (sub == 0) { curx = lx; cury = ly; }
                else          { nxtx = lx; nxty = ly; }
            }
            // 11-tap vertical conv (packed, squares on the fly)
            u64 ms, md, es, ed;
            {
                const int s0 = rr % 11;
                u64 sv = rs[s0], dv = rd[s0];
                ms = mul2(WV0, sv);
                md = mul2(WV0, dv);
                es = mul2(WV0, mul2(sv, sv));
                ed = mul2(WV0, mul2(dv, dv));
            }
            #pragma unroll
            for (int tt = 1; tt < 11; tt++) {
                const int sl = (rr + tt) % 11;
                const u64 w = (tt == 1 || tt == 9) ? WV1 :
                              (tt == 2 || tt == 8) ? WV2 :
                              (tt == 3 || tt == 7) ? WV3 :
                              (tt == 4 || tt == 6) ? WV4 :
                              (tt == 5)            ? WV5 : WV0;
                u64 sv = rs[sl], dv = rd[sl];
                ms = fma2(w, sv, ms);
                md = fma2(w, dv, md);
                es = fma2(w, mul2(sv, sv), es);
                ed = fma2(w, mul2(dv, dv), ed);
            }
            const int buf = 2 * pb + sub;
            *(u64*)(&vbuf[buf][0][8 + c0]) = ms;
            *(u64*)(&vbuf[buf][1][8 + c0]) = md;
            *(u64*)(&vbuf[buf][2][8 + c0]) = es;
            *(u64*)(&vbuf[buf][3][8 + c0]) = ed;
            if (sub == 1) { oms = ms; omd = md; oes = es; oed = ed; }
        }

        __syncthreads();   // one barrier per 2 rows

        // ---- horizontal pass + SSIM for both rows (scalar FFMA-imm) ----
        #pragma unroll
        for (int sub = 0; sub < 2; sub++) {
            const int buf = 2 * pb + sub;
            const u64 ownv[4] = {oms, omd, oes, oed};
            u64 hr2[4];
            #pragma unroll
            for (int q = 0; q < 4; q++) {
                const float2* vb = (const float2*)(&vbuf[buf][q][8 + c0 - 6]);
                float2 f0 = vb[0];   // v[-6], v[-5]
                float2 f1 = vb[1];   // v[-4], v[-3]
                float2 f2 = vb[2];   // v[-2], v[-1]
                float2 f3;           // v[0],  v[1]  (own pair)
                if (sub == 1) { unpack2(ownv[q], f3.x, f3.y); }
                else          { f3 = vb[3]; }
                float2 f4 = vb[4];   // v[2],  v[3]
                float2 f5 = vb[5];   // v[4],  v[5]
                float2 f6 = vb[6];   // v[6],  v[7]

                float p0 = KW0 * f0.y;
                p0 = fmaf(KW1, f1.x, p0);
                p0 = fmaf(KW2, f1.y, p0);
                p0 = fmaf(KW3, f2.x, p0);
                p0 = fmaf(KW4, f2.y, p0);
                p0 = fmaf(KW5, f3.x, p0);
                p0 = fmaf(KW4, f3.y, p0);
                p0 = fmaf(KW3, f4.x, p0);
                p0 = fmaf(KW2, f4.y, p0);
                p0 = fmaf(KW1, f5.x, p0);
                p0 = fmaf(KW0, f5.y, p0);

                float p1 = KW0 * f1.x;
                p1 = fmaf(KW1, f1.y, p1);
                p1 = fmaf(KW2, f2.x, p1);
                p1 = fmaf(KW3, f2.y, p1);
                p1 = fmaf(KW4, f3.x, p1);
                p1 = fmaf(KW5, f3.y, p1);
                p1 = fmaf(KW4, f4.x, p1);
                p1 = fmaf(KW3, f4.y, p1);
                p1 = fmaf(KW2, f5.x, p1);
                p1 = fmaf(KW1, f5.y, p1);
                p1 = fmaf(KW0, f6.x, p1);

                hr2[q] = pack2(p0, p1);
            }

            // ---- SSIM, x4-scaled (bit-identical quotient) ----
            {
                u64 MS = hr2[0], MD = hr2[1], ES = hr2[2], ED = hr2[3];
                u64 A  = mul2(MS, MS);
                u64 B  = mul2(MD, MD);
                u64 P2 = add2(A, B);                    // 2(mu1^2+mu2^2)
                u64 Q2 = fma2(B, NEG1v, A);             // 4*mu1*mu2
                u64 SE = add2(ES, ED);
                u64 DE = fma2(ED, NEG1v, ES);
                u64 R2 = fma2(P2, NEG1v, SE);           // 2(sig1+sig2)
                u64 T2 = fma2(Q2, NEG1v, DE);           // 4*sig12
                u64 num = mul2(add2(Q2, C1x2), add2(T2, C2x2));
                u64 den = mul2(add2(P2, C1x2), add2(R2, C2x2));
                float dlo, dhi;
                unpack2(den, dlo, dhi);
                u64 rcpv = pack2(frcp(dlo), frcp(dhi));
                accv = fma2(num, rcpv, accv);
            }
        }
    }

    float alo, ahi;
    unpack2(accv, alo, ahi);
    float acc = alo + ahi;

    // ---- deterministic block reduction ----
    #pragma unroll
    for (int off = 16; off > 0; off >>= 1)
        acc += __shfl_xor_sync(0xffffffffu, acc, off);
    if ((t & 31) == 0) warpsum[t >> 5] = acc;
    __syncthreads();
    if (t == 0) {
        float s = 0.0f;
        #pragma unroll
        for (int i = 0; i < 8; i++) s += warpsum[i];
        g_partials[b] = (double)s;
    }

    // ---- fused finalize: last block sums all partials (deterministic) ----
    __threadfence();
    if (t == 0) {
        unsigned int old = atomicAdd(&g_ticket, 1u);
        is_last = (old == NBLOCKS - 1);
    }
    __syncthreads();
    if (is_last) {
        double sm = 0.0;
        for (int i = t; i < NBLOCKS; i += NTHREADS) sm += g_partials[i];
        sd[t] = sm;
        __syncthreads();
        #pragma unroll
        for (int off = NTHREADS / 2; off > 0; off >>= 1) {
            if (t < off) sd[t] += sd[t + off];
            __syncthreads();
        }
        if (t == 0) {
            out[0] = (float)(1.0 - sd[0] / TOTAL_PIX);
            g_ticket = 0;   // reset for next graph replay
        }
    }
}

extern "C" void kernel_launch(void* const* d_in, const int* in_sizes, int n_in,
                              void* d_out, int out_size) {
    const float* clean = (const float*)d_in[0];
    const float* adv   = (const float*)d_in[1];
    ssim_main<<<NBLOCKS, NTHREADS>>>(clean, adv, (float*)d_out);
}